// round 7
// baseline (speedup 1.0000x reference)
#include <cuda_runtime.h>

#define BATCH    16
#define NROWS    25200
#define NCOLS    85
#define MAXDET   300
#define CTHRES   0.25f
#define NTHREADS 512
#define NWARPS   (NTHREADS / 32)   // 16
#define NSLICES  9
#define NGMAX    11                // ceil(66*85 / 512)

// Balanced slice boundaries: early slices own many slots (short scans),
// late slices few slots (long scans).
__device__ __constant__ int d_clo[NSLICES] = {0, 66, 119, 163, 199, 228, 252, 272, 288};
__device__ __constant__ int d_chi[NSLICES] = {66, 119, 163, 199, 228, 252, 272, 288, 300};
// Tightened scan bounds (>=5.2 sigma margin each); fallback loop preserves
// correctness for arbitrary data — a missed bound only costs extra chunks.
__device__ __constant__ int d_u[NSLICES]   = {160, 256, 320, 352, 400, 416, 432, 448, 464};

__global__ __launch_bounds__(NTHREADS, 2)
void compact_kernel(const float* __restrict__ pred, float* __restrict__ out)
{
    __shared__ int s_order[MAXDET];
    __shared__ int s_cnt[NWARPS];

    const int b     = blockIdx.x / NSLICES;
    const int slice = blockIdx.x % NSLICES;
    const int tid   = threadIdx.x;
    const int lane  = tid & 31;
    const int warp  = tid >> 5;

    const int lo = d_clo[slice];
    const int hi = d_chi[slice];
    const int u  = d_u[slice];
    const unsigned lanemask = (1u << lane) - 1u;

    const float* bpred = pred + (long long)b * NROWS * NCOLS;

    int base;

    // ---- chunk 1: rows [0, u) — expected to be the ONLY chunk ----
    {
        bool m = false;
        if (tid < u)
            m = __ldg(&bpred[(long long)tid * NCOLS + 4]) > CTHRES;

        unsigned bal = __ballot_sync(0xffffffffu, m);
        if (lane == 0) s_cnt[warp] = __popc(bal);
        __syncthreads();                        // barrier #1 (only one in scan)

        // Every warp redundantly scans the 16 warp counts — no 2nd barrier.
        int v = (lane < NWARPS) ? s_cnt[lane] : 0;
        int inc = v;
        #pragma unroll
        for (int o = 1; o < NWARPS; o <<= 1) {
            int t = __shfl_up_sync(0xffffffffu, inc, o);
            if (lane >= o) inc += t;
        }
        int total = __shfl_sync(0xffffffffu, inc, NWARPS - 1);
        int wpre  = (warp == 0) ? 0 : __shfl_sync(0xffffffffu, inc, warp - 1);

        if (m) {
            int rank = wpre + __popc(bal & lanemask);
            if (rank < MAXDET) s_order[rank] = tid;
        }
        base = total;
    }

    // ---- fallback: only if chunk 1 didn't cover this slice (statistically never) ----
    int row0 = u;
    while (base < hi && row0 < NROWS) {
        __syncthreads();    // protect s_cnt rewrite vs prior reads
        int i = row0 + tid;
        bool m = false;
        if (i < NROWS)
            m = __ldg(&bpred[(long long)i * NCOLS + 4]) > CTHRES;

        unsigned bal = __ballot_sync(0xffffffffu, m);
        if (lane == 0) s_cnt[warp] = __popc(bal);
        __syncthreads();

        int v = (lane < NWARPS) ? s_cnt[lane] : 0;
        int inc = v;
        #pragma unroll
        for (int o = 1; o < NWARPS; o <<= 1) {
            int t = __shfl_up_sync(0xffffffffu, inc, o);
            if (lane >= o) inc += t;
        }
        int total = __shfl_sync(0xffffffffu, inc, NWARPS - 1);
        int wpre  = (warp == 0) ? 0 : __shfl_sync(0xffffffffu, inc, warp - 1);

        if (m) {
            int rank = base + wpre + __popc(bal & lanemask);
            if (rank < MAXDET) s_order[rank] = i;
        }
        base += total;
        row0 += NTHREADS;
    }
    __syncthreads();        // barrier #2: s_order visible to all warps

    int cnt = base;
    if (cnt > MAXDET) cnt = MAXDET;

    const int nslots = hi - lo;
    float* bout = out + (long long)b * MAXDET * NCOLS + (long long)lo * NCOLS;

    // Gather slots [lo, hi). Division-free: one initial div, then incremental
    // (sl, col) update per step (NTHREADS = 6*NCOLS + 2).
    int sl  = tid / NCOLS;      // 0..6
    int col = tid - sl * NCOLS;

    int  src_k[NGMAX];
    int  col_k[NGMAX];
    bool ok_k[NGMAX];
    {
        int sl_i = sl, col_i = col;
        #pragma unroll
        for (int k = 0; k < NGMAX; ++k) {
            int slot = lo + sl_i;
            ok_k[k]  = (sl_i < nslots) && (slot < cnt);
            col_k[k] = col_i;
            src_k[k] = ok_k[k] ? s_order[slot] : 0;
            sl_i  += 6;
            col_i += 2;
            if (col_i >= NCOLS) { col_i -= NCOLS; sl_i += 1; }
        }
    }
    float v_k[NGMAX];
    #pragma unroll
    for (int k = 0; k < NGMAX; ++k)
        v_k[k] = ok_k[k] ? __ldg(&bpred[(long long)src_k[k] * NCOLS + col_k[k]]) : 0.0f;

    {
        int sl_i = sl, col_i = col;
        int e = tid;
        #pragma unroll
        for (int k = 0; k < NGMAX; ++k) {
            if (sl_i < nslots) bout[e] = v_k[k];
            e     += NTHREADS;
            sl_i  += 6;
            col_i += 2;
            if (col_i >= NCOLS) { col_i -= NCOLS; sl_i += 1; }
        }
    }
}

extern "C" void kernel_launch(void* const* d_in, const int* in_sizes, int n_in,
                              void* d_out, int out_size)
{
    const float* pred = (const float*)d_in[0];
    float* out = (float*)d_out;
    compact_kernel<<<BATCH * NSLICES, NTHREADS>>>(pred, out);
}

// round 8
// speedup vs baseline: 1.0385x; 1.0385x over previous
#include <cuda_runtime.h>

#define BATCH    16
#define NROWS    25200
#define NCOLS    85
#define MAXDET   300
#define CTHRES   0.25f
#define NTHREADS 512
#define NWARPS   (NTHREADS / 32)   // 16
#define NSLICES  9
#define NGMAX    11                // ceil(66*85 / 512)
#define WMAX     128               // max window rows (43.5KB smem)

// Balanced slice boundaries.
__device__ __constant__ int d_clo[NSLICES] = {0, 66, 119, 163, 199, 228, 252, 272, 288};
__device__ __constant__ int d_chi[NSLICES] = {66, 119, 163, 199, 228, 252, 272, 288, 300};
// Scan bound per slice (>=5 sigma); fallback loop keeps correctness unconditional.
__device__ __constant__ int d_u[NSLICES]   = {160, 256, 320, 352, 400, 416, 432, 448, 464};
// Speculative gather window [w_lo, w_lo+w_n): covers expected rows of ranks
// [lo,hi) with >=3.4 sigma margins. Rows outside window use gmem fallback.
// w_lo multiple of 4 => 16B-aligned cp.async; w_n*85 divisible by 4.
__device__ __constant__ int d_wlo[NSLICES] = {0, 56, 128, 184, 232, 272, 304, 328, 344};
__device__ __constant__ int d_wn[NSLICES]  = {128, 128, 120, 120, 120, 112, 112, 112, 120};

__device__ __forceinline__ unsigned smem_u32(const void* p) {
    return (unsigned)__cvta_generic_to_shared(p);
}

__global__ __launch_bounds__(NTHREADS, 2)
void compact_kernel(const float* __restrict__ pred, float* __restrict__ out)
{
    __shared__ float s_buf[WMAX * NCOLS];   // speculative gather window
    __shared__ int   s_order[MAXDET];
    __shared__ int   s_cnt[NWARPS];

    const int b     = blockIdx.x / NSLICES;
    const int slice = blockIdx.x % NSLICES;
    const int tid   = threadIdx.x;
    const int lane  = tid & 31;
    const int warp  = tid >> 5;

    const int lo   = d_clo[slice];
    const int hi   = d_chi[slice];
    const int u    = d_u[slice];
    const int w_lo = d_wlo[slice];
    const int w_n  = d_wn[slice];
    const int w_hi = w_lo + w_n;
    const unsigned lanemask = (1u << lane) - 1u;

    const float* bpred = pred + (long long)b * NROWS * NCOLS;

    // ---- stage window rows [w_lo, w_hi) into smem, async (overlaps conf round) ----
    {
        const float* gsrc = bpred + (long long)w_lo * NCOLS;   // 16B aligned
        const int nq = (w_n * NCOLS) / 4;                      // float4 count
        #pragma unroll
        for (int k = 0; k < 6; ++k) {
            int idx = k * NTHREADS + tid;
            if (idx < nq) {
                unsigned saddr = smem_u32(&s_buf[idx * 4]);
                const float4* g = (const float4*)gsrc + idx;
                asm volatile("cp.async.cg.shared.global [%0], [%1], 16;\n"
                             :: "r"(saddr), "l"(g));
            }
        }
        asm volatile("cp.async.commit_group;\n");
    }

    int base;

    // ---- chunk 1: conf scan of rows [0, u) — expected to be the ONLY chunk ----
    {
        bool m = false;
        if (tid < u)
            m = __ldg(&bpred[(long long)tid * NCOLS + 4]) > CTHRES;

        unsigned bal = __ballot_sync(0xffffffffu, m);
        if (lane == 0) s_cnt[warp] = __popc(bal);
        __syncthreads();

        int v = (lane < NWARPS) ? s_cnt[lane] : 0;
        int inc = v;
        #pragma unroll
        for (int o = 1; o < NWARPS; o <<= 1) {
            int t = __shfl_up_sync(0xffffffffu, inc, o);
            if (lane >= o) inc += t;
        }
        int total = __shfl_sync(0xffffffffu, inc, NWARPS - 1);
        int wpre  = (warp == 0) ? 0 : __shfl_sync(0xffffffffu, inc, warp - 1);

        if (m) {
            int rank = wpre + __popc(bal & lanemask);
            if (rank < MAXDET) s_order[rank] = tid;
        }
        base = total;
    }

    // ---- fallback: only if chunk 1 didn't cover this slice (statistically never) ----
    int row0 = u;
    while (base < hi && row0 < NROWS) {
        __syncthreads();
        int i = row0 + tid;
        bool m = false;
        if (i < NROWS)
            m = __ldg(&bpred[(long long)i * NCOLS + 4]) > CTHRES;

        unsigned bal = __ballot_sync(0xffffffffu, m);
        if (lane == 0) s_cnt[warp] = __popc(bal);
        __syncthreads();

        int v = (lane < NWARPS) ? s_cnt[lane] : 0;
        int inc = v;
        #pragma unroll
        for (int o = 1; o < NWARPS; o <<= 1) {
            int t = __shfl_up_sync(0xffffffffu, inc, o);
            if (lane >= o) inc += t;
        }
        int total = __shfl_sync(0xffffffffu, inc, NWARPS - 1);
        int wpre  = (warp == 0) ? 0 : __shfl_sync(0xffffffffu, inc, warp - 1);

        if (m) {
            int rank = base + wpre + __popc(bal & lanemask);
            if (rank < MAXDET) s_order[rank] = i;
        }
        base += total;
        row0 += NTHREADS;
    }

    // Window data + s_order both visible after this barrier.
    asm volatile("cp.async.wait_group 0;\n");
    __syncthreads();

    int cnt = base;
    if (cnt > MAXDET) cnt = MAXDET;

    const int nslots = hi - lo;
    float* bout = out + (long long)b * MAXDET * NCOLS + (long long)lo * NCOLS;

    // Gather slots [lo, hi) — smem fast path, gmem fallback outside window.
    int sl  = tid / NCOLS;      // 0..6
    int col = tid - sl * NCOLS;

    float v_k[NGMAX];
    {
        int sl_i = sl, col_i = col;
        #pragma unroll
        for (int k = 0; k < NGMAX; ++k) {
            float v = 0.0f;
            int slot = lo + sl_i;
            if (sl_i < nslots && slot < cnt) {
                int src = s_order[slot];
                if (src >= w_lo && src < w_hi)
                    v = s_buf[(src - w_lo) * NCOLS + col_i];
                else
                    v = __ldg(&bpred[(long long)src * NCOLS + col_i]);
            }
            v_k[k] = v;
            sl_i  += 6;
            col_i += 2;
            if (col_i >= NCOLS) { col_i -= NCOLS; sl_i += 1; }
        }
    }
    {
        int sl_i = sl;
        int e = tid;
        #pragma unroll
        for (int k = 0; k < NGMAX; ++k) {
            if (sl_i < nslots) bout[e] = v_k[k];
            e += NTHREADS;
            sl_i += 6;
            int c2 = (e - sl_i * NCOLS);  // keep col in sync cheaply
            if (c2 >= NCOLS) { sl_i += 1; }
        }
    }
}

extern "C" void kernel_launch(void* const* d_in, const int* in_sizes, int n_in,
                              void* d_out, int out_size)
{
    const float* pred = (const float*)d_in[0];
    float* out = (float*)d_out;
    compact_kernel<<<BATCH * NSLICES, NTHREADS>>>(pred, out);
}